// round 2
// baseline (speedup 1.0000x reference)
#include <cuda_runtime.h>

// -------- static scratch (no allocations allowed) --------
#define CAP   64
#define MAXN  16384

__device__ int   g_cnt[MAXN];
__device__ float g_rowsum[MAXN];
__device__ int   g_colbuf[MAXN * CAP];
__device__ float g_valbuf[MAXN * CAP];

// Zero the whole output buffer (A then b region) and reset per-row scratch.
__global__ void k_zero(float* __restrict__ out, long total, int n) {
    long i      = (long)blockIdx.x * blockDim.x + threadIdx.x;
    long stride = (long)gridDim.x * blockDim.x;
    long n4 = total >> 2;
    float4* o4 = (float4*)out;
    float4 z = make_float4(0.f, 0.f, 0.f, 0.f);
    for (long p = i; p < n4; p += stride) o4[p] = z;
    if (i < (total & 3)) out[n4 * 4 + i] = 0.f;
    if (i < n) { g_cnt[i] = 0; g_rowsum[i] = 0.f; }
}

// Scatter Wcm COO entries (row-scaled by CM_weights) into per-row buckets
// and accumulate row sums.
__global__ void k_scatter_cm(const int* __restrict__ row,
                             const int* __restrict__ col,
                             const float* __restrict__ data,
                             const float* __restrict__ cmw, int nnz) {
    int t = blockIdx.x * blockDim.x + threadIdx.x;
    if (t >= nnz) return;
    int r = row[t];
    float v = data[t] * cmw[r];
    int slot = atomicAdd(&g_cnt[r], 1);
    if (slot < CAP) {
        g_colbuf[r * CAP + slot] = col[t];
        g_valbuf[r * CAP + slot] = v;
    }
    atomicAdd(&g_rowsum[r], v);
}

// For each row k of Lcm, emit all pair products into A += Lcm^T Lcm.
// Row k entries: (c_i, -w_i) for each nnz, plus virtual diagonal (k, rowsum_k).
// Duplicate columns need no merging: sum over entry-pairs == product of sums.
__global__ void k_cm_pairs(float* __restrict__ A, int n) {
    __shared__ int   scol[8][CAP + 1];
    __shared__ float sval[8][CAP + 1];
    int w = threadIdx.x >> 5, lane = threadIdx.x & 31;
    int r = blockIdx.x * 8 + w;
    if (r >= n) return;
    int cnt = g_cnt[r];
    if (cnt > CAP) cnt = CAP;
    for (int i = lane; i < cnt; i += 32) {
        scol[w][i] = g_colbuf[r * CAP + i];
        sval[w][i] = -g_valbuf[r * CAP + i];
    }
    if (lane == 0) { scol[w][cnt] = r; sval[w][cnt] = g_rowsum[r]; }
    __syncwarp();
    int tot = cnt + 1;
    int pairs = tot * tot;
    for (int p = lane; p < pairs; p += 32) {
        int i = p / tot;
        int j = p - i * tot;
        float prod = sval[w][i] * sval[w][j];
        atomicAdd(&A[(size_t)scol[w][i] * n + scol[w][j]], prod);
    }
}

// LOC term: W[r, c] += v with r = ind-1-width, c = ind + off_j,
// v = LOC_flows[j,0,m] * LOC_weights[ind]. Then Wsym = 0.5(W+W^T),
// Lmat = diag(rowsum(Wsym)) - Wsym, folded into 4 atomic adds per entry.
__global__ void k_loc(float* __restrict__ A,
                      const int* __restrict__ inInd,
                      const float* __restrict__ flows,
                      const float* __restrict__ locw,
                      int m, int n, const int* __restrict__ widthp) {
    int t = blockIdx.x * blockDim.x + threadIdx.x;
    if (t >= m * 9) return;
    int mi = t / 9, j = t - mi * 9;
    int W = widthp[0];
    int ind = inInd[mi];
    // offs = [-1-W,-1,-1+W,-W,0,W,1-W,1,1+W] == (j/3-1) + (j%3-1)*W
    int off = (j / 3 - 1) + (j % 3 - 1) * W;
    float v = flows[(size_t)j * 9 * m + mi] * locw[ind];
    int r = ind - 1 - W;
    int c = ind + off;
    float h = 0.5f * v;
    atomicAdd(&A[(size_t)r * n + c], -h);
    atomicAdd(&A[(size_t)c * n + r], -h);
    atomicAdd(&A[(size_t)r * n + r],  h);
    atomicAdd(&A[(size_t)c * n + c],  h);
}

// IU term: same symmetrized-Laplacian fold, 5 neighbors per index.
__global__ void k_iu(float* __restrict__ A,
                     const int* __restrict__ inInd,
                     const float* __restrict__ flows,
                     const int* __restrict__ neigh,
                     const float* __restrict__ iuw,
                     int m, int n) {
    int t = blockIdx.x * blockDim.x + threadIdx.x;
    if (t >= m * 5) return;
    int mi = t / 5, j = t - mi * 5;
    int r = inInd[mi];
    float v = flows[mi * 5 + j] * iuw[r];
    int c = neigh[mi * 5 + j];
    float h = 0.5f * v;
    atomicAdd(&A[(size_t)r * n + c], -h);
    atomicAdd(&A[(size_t)c * n + r], -h);
    atomicAdd(&A[(size_t)r * n + r],  h);
    atomicAdd(&A[(size_t)c * n + c],  h);
}

// Diagonal regularization terms + b vector.
__global__ void k_diag_b(float* __restrict__ A, float* __restrict__ b,
                         const float* __restrict__ ku,
                         const float* __restrict__ conf,
                         const float* __restrict__ lmb,
                         const float* __restrict__ known,
                         const float* __restrict__ kToU, int n) {
    int i = blockIdx.x * blockDim.x + threadIdx.x;
    if (i >= n) return;
    float d = ku[i] * conf[i] + lmb[0] * known[i];
    atomicAdd(&A[(size_t)i * n + i], d);
    b[i] = d * kToU[i];
}

extern "C" void kernel_launch(void* const* d_in, const int* in_sizes, int n_in,
                              void* d_out, int out_size) {
    // metadata order:
    // 0 height, 1 width, 2 CM_weights, 3 LOC_weights, 4 IU_weights,
    // 5 KU_weights, 6 lmbda, 7 kToUconf, 8 known, 9 kToU,
    // 10 Wcm_row, 11 Wcm_col, 12 Wcm_data, 13 LOC_inInd, 14 LOC_flows,
    // 15 IU_inInd, 16 IU_flows, 17 IU_neighInd
    const int*   width   = (const int*)d_in[1];
    const float* CMw     = (const float*)d_in[2];
    const float* LOCw    = (const float*)d_in[3];
    const float* IUw     = (const float*)d_in[4];
    const float* KUw     = (const float*)d_in[5];
    const float* lmbda   = (const float*)d_in[6];
    const float* conf    = (const float*)d_in[7];
    const float* known   = (const float*)d_in[8];
    const float* kToU    = (const float*)d_in[9];
    const int*   wr      = (const int*)d_in[10];
    const int*   wc      = (const int*)d_in[11];
    const float* wd      = (const float*)d_in[12];
    const int*   locInd  = (const int*)d_in[13];
    const float* locFl   = (const float*)d_in[14];
    const int*   iuInd   = (const int*)d_in[15];
    const float* iuFl    = (const float*)d_in[16];
    const int*   iuNb    = (const int*)d_in[17];

    int N    = in_sizes[2];
    int NNZ  = in_sizes[10];
    int MLOC = in_sizes[13];
    int MIU  = in_sizes[15];

    float* A = (float*)d_out;
    float* b = A + (size_t)N * N;
    long total = (long)out_size;

    long n4 = total >> 2;
    int gz = (int)((n4 + 255) / 256);
    if (gz > 16384) gz = 16384;
    int gmin = (N + 255) / 256;
    if (gz < gmin) gz = gmin;
    if (gz < 1) gz = 1;

    k_zero<<<gz, 256>>>(A, total, N);
    k_scatter_cm<<<(NNZ + 255) / 256, 256>>>(wr, wc, wd, CMw, NNZ);
    k_cm_pairs<<<(N + 7) / 8, 256>>>(A, N);
    k_loc<<<(MLOC * 9 + 255) / 256, 256>>>(A, locInd, locFl, LOCw, MLOC, N, width);
    k_iu<<<(MIU * 5 + 255) / 256, 256>>>(A, iuInd, iuFl, iuNb, IUw, MIU, N);
    k_diag_b<<<(N + 255) / 256, 256>>>(A, b, KUw, conf, lmbda, known, kToU, N);
}

// round 4
// speedup vs baseline: 1.1348x; 1.1348x over previous
#include <cuda_runtime.h>

// -------- static scratch (no allocations allowed) --------
// Zero-initialized at module load; K2 resets it after use, so every call
// (including the first) observes zeroed counters/rowsums.
#define CAP   64
#define MAXN  16384

__device__ int   g_cnt[MAXN];
__device__ float g_rowsum[MAXN];
__device__ int   g_colbuf[MAXN * CAP];
__device__ float g_valbuf[MAXN * CAP];

// ===================== K1: zero output  +  CM COO scatter ====================
// Blocks [0, nbScat) scatter Wcm entries into per-row buckets (scratch only).
// Blocks [nbScat, nbScat+nbZero) zero the whole output buffer (A then b).
// The two halves touch disjoint memory -> safe to run concurrently.
__global__ void k1_zero_scatter(float* __restrict__ out, long total,
                                const int* __restrict__ row,
                                const int* __restrict__ col,
                                const float* __restrict__ data,
                                const float* __restrict__ cmw,
                                int nnz, int nbScat, int nbZero) {
    int b = blockIdx.x;
    if (b < nbScat) {
        int t = b * blockDim.x + threadIdx.x;
        if (t >= nnz) return;
        int r = row[t];
        float v = data[t] * cmw[r];
        int slot = atomicAdd(&g_cnt[r], 1);
        if (slot < CAP) {
            g_colbuf[r * CAP + slot] = col[t];
            g_valbuf[r * CAP + slot] = v;
        }
        atomicAdd(&g_rowsum[r], v);
    } else {
        long i      = (long)(b - nbScat) * blockDim.x + threadIdx.x;
        long stride = (long)nbZero * blockDim.x;
        long n4 = total >> 2;
        float4* o4 = (float4*)out;
        float4 z = make_float4(0.f, 0.f, 0.f, 0.f);
        for (long p = i; p < n4; p += stride) o4[p] = z;
        if (i < (total & 3)) out[n4 * 4 + i] = 0.f;
    }
}

// ===================== K2: all accumulation into A, plus b ===================
// Block roles by blockIdx range:
//   [0, nbPairs)                      : Lcm^T Lcm pair scatter (warp per row),
//                                       then reset that row's scratch.
//   [nbPairs, +nbLoc)                 : LOC symmetrized Laplacian (thread/mi).
//   [.., +nbIu)                       : IU  symmetrized Laplacian (thread/mi).
//   [.., +nbDiag)                     : diag regularization + b vector.
__global__ void k2_accumulate(float* __restrict__ A, float* __restrict__ bvec,
                              int n,
                              // loc
                              const int* __restrict__ locInd,
                              const float* __restrict__ locFl,
                              const float* __restrict__ locw,
                              int mloc, const int* __restrict__ widthp,
                              // iu
                              const int* __restrict__ iuInd,
                              const float* __restrict__ iuFl,
                              const int* __restrict__ iuNb,
                              const float* __restrict__ iuw,
                              int miu,
                              // diag
                              const float* __restrict__ ku,
                              const float* __restrict__ conf,
                              const float* __restrict__ lmb,
                              const float* __restrict__ known,
                              const float* __restrict__ kToU,
                              int nbPairs, int nbLoc, int nbIu) {
    int b = blockIdx.x;

    if (b < nbPairs) {
        // ---- Lcm^T Lcm: warp per row. Row k of Lcm has entries
        // (c_i, -w_i) plus virtual diagonal (k, rowsum_k). COO duplicates
        // need no merging: sum over entry pairs == product of sums.
        __shared__ int   scol[8][CAP + 2];
        __shared__ float sval[8][CAP + 2];
        int w = threadIdx.x >> 5, lane = threadIdx.x & 31;
        int r = b * 8 + w;
        if (r >= n) return;
        int cnt = g_cnt[r];
        if (cnt > CAP) cnt = CAP;
        for (int i = lane; i < cnt; i += 32) {
            scol[w][i] = g_colbuf[r * CAP + i];
            sval[w][i] = -g_valbuf[r * CAP + i];
        }
        if (lane == 0) {
            scol[w][cnt] = r;
            sval[w][cnt] = g_rowsum[r];
            // reset scratch for next call
            g_cnt[r] = 0;
            g_rowsum[r] = 0.f;
        }
        __syncwarp();
        int tot = cnt + 1;
        int pairs = tot * tot;
        for (int p = lane; p < pairs; p += 32) {
            int i = p / tot;
            int j = p - i * tot;
            atomicAdd(&A[(size_t)scol[w][i] * n + scol[w][j]],
                      sval[w][i] * sval[w][j]);
        }
        return;
    }
    b -= nbPairs;

    if (b < nbLoc) {
        // ---- LOC: one thread per mi, loop over 9 neighbors.
        int mi = b * blockDim.x + threadIdx.x;
        if (mi >= mloc) return;
        int W = widthp[0];
        int ind = locInd[mi];
        float wv = locw[ind];
        int r = ind - 1 - W;
        size_t rn = (size_t)r * n;
        float diag_r = 0.f;
        #pragma unroll
        for (int j = 0; j < 9; j++) {
            int off = (j / 3 - 1) + (j % 3 - 1) * W;
            int c = ind + off;
            float h = 0.5f * locFl[(size_t)j * 9 * mloc + mi] * wv;
            atomicAdd(&A[rn + c], -h);
            atomicAdd(&A[(size_t)c * n + r], -h);
            atomicAdd(&A[(size_t)c * n + c],  h);
            diag_r += h;
        }
        atomicAdd(&A[rn + r], diag_r);
        return;
    }
    b -= nbLoc;

    if (b < nbIu) {
        // ---- IU: one thread per mi, loop over 5 neighbors.
        int mi = b * blockDim.x + threadIdx.x;
        if (mi >= miu) return;
        int r = iuInd[mi];
        float wv = iuw[r];
        size_t rn = (size_t)r * n;
        float diag_r = 0.f;
        #pragma unroll
        for (int j = 0; j < 5; j++) {
            float h = 0.5f * iuFl[mi * 5 + j] * wv;
            int c = iuNb[mi * 5 + j];
            atomicAdd(&A[rn + c], -h);
            atomicAdd(&A[(size_t)c * n + r], -h);
            atomicAdd(&A[(size_t)c * n + c],  h);
            diag_r += h;
        }
        atomicAdd(&A[rn + r], diag_r);
        return;
    }
    b -= nbIu;

    // ---- diagonal regularization + b
    int i = b * blockDim.x + threadIdx.x;
    if (i >= n) return;
    float d = ku[i] * conf[i] + lmb[0] * known[i];
    atomicAdd(&A[(size_t)i * n + i], d);
    bvec[i] = d * kToU[i];
}

extern "C" void kernel_launch(void* const* d_in, const int* in_sizes, int n_in,
                              void* d_out, int out_size) {
    // metadata order:
    // 0 height, 1 width, 2 CM_weights, 3 LOC_weights, 4 IU_weights,
    // 5 KU_weights, 6 lmbda, 7 kToUconf, 8 known, 9 kToU,
    // 10 Wcm_row, 11 Wcm_col, 12 Wcm_data, 13 LOC_inInd, 14 LOC_flows,
    // 15 IU_inInd, 16 IU_flows, 17 IU_neighInd
    const int*   width   = (const int*)d_in[1];
    const float* CMw     = (const float*)d_in[2];
    const float* LOCw    = (const float*)d_in[3];
    const float* IUw     = (const float*)d_in[4];
    const float* KUw     = (const float*)d_in[5];
    const float* lmbda   = (const float*)d_in[6];
    const float* conf    = (const float*)d_in[7];
    const float* known   = (const float*)d_in[8];
    const float* kToU    = (const float*)d_in[9];
    const int*   wr      = (const int*)d_in[10];
    const int*   wc      = (const int*)d_in[11];
    const float* wd      = (const float*)d_in[12];
    const int*   locInd  = (const int*)d_in[13];
    const float* locFl   = (const float*)d_in[14];
    const int*   iuInd   = (const int*)d_in[15];
    const float* iuFl    = (const float*)d_in[16];
    const int*   iuNb    = (const int*)d_in[17];

    int N    = in_sizes[2];
    int NNZ  = in_sizes[10];
    int MLOC = in_sizes[13];
    int MIU  = in_sizes[15];

    float* A = (float*)d_out;
    float* b = A + (size_t)N * N;
    long total = (long)out_size;

    const int T = 256;
    int nbScat = (NNZ + T - 1) / T;
    int nbZero = 2048;
    k1_zero_scatter<<<nbScat + nbZero, T>>>(A, total, wr, wc, wd, CMw,
                                            NNZ, nbScat, nbZero);

    int nbPairs = (N + 7) / 8;
    int nbLoc   = (MLOC + T - 1) / T;
    int nbIu    = (MIU + T - 1) / T;
    int nbDiag  = (N + T - 1) / T;
    k2_accumulate<<<nbPairs + nbLoc + nbIu + nbDiag, T>>>(
        A, b, N,
        locInd, locFl, LOCw, MLOC, width,
        iuInd, iuFl, iuNb, IUw, MIU,
        KUw, conf, lmbda, known, kToU,
        nbPairs, nbLoc, nbIu);
}